// round 8
// baseline (speedup 1.0000x reference)
#include <cuda_runtime.h>
#include <cuda_bf16.h>

// word_vecs [B=2048, S=200, D=300] fp32 -> masked mean over S -> [B, D].
// All-zero words contribute 0 to the sum, so only the COUNT needs the mask.
//
// Single-wave variant: the kernel is pinned at the full-chip LTS cap
// (~6.35 TB/s); the only remaining loss is the straggler wave (2048 CTAs vs
// ~1900 concurrent). grid=1024, each CTA handles 2 sentences sequentially ->
// one perfectly balanced wave, no tail. Hot loop identical to the best kernel:
// float4 + __ldcs, unroll 4, per-word pacing, predicated same-value flag store.

#define B_DIM 2048
#define GRID  1024
#define S_DIM 200
#define VDIM  75   // 300 floats = 75 float4 per word (1200 B, 16B-aligned)
#define NTHREADS 96

__global__ __launch_bounds__(NTHREADS)
void sentence_rep_kernel(const float4* __restrict__ in, float4* __restrict__ out) {
    __shared__ unsigned char flags[S_DIM];
    __shared__ float inv_count;

    const int t = threadIdx.x;
    const bool active = (t < VDIM);

    #pragma unroll 1
    for (int rep = 0; rep < 2; ++rep) {
        const int b = blockIdx.x + rep * GRID;

        for (int i = t; i < S_DIM; i += NTHREADS) flags[i] = 0;
        __syncthreads();

        const float4* __restrict__ row = in + (size_t)b * (S_DIM * VDIM);

        float4 acc = make_float4(0.f, 0.f, 0.f, 0.f);

        #pragma unroll 4
        for (int s = 0; s < S_DIM; ++s) {
            float4 v = make_float4(0.f, 0.f, 0.f, 0.f);
            if (active) v = __ldcs(&row[s * VDIM + t]);
            acc.x += v.x; acc.y += v.y; acc.z += v.z; acc.w += v.w;

            // any-nonzero -> flag (multi-lane same-value STS collapses; benign)
            bool nz = (v.x != 0.f) || (v.y != 0.f) || (v.z != 0.f) || (v.w != 0.f);
            if (nz) flags[s] = 1;
        }
        __syncthreads();

        if (t < 32) {
            int c = 0;
            for (int i = t; i < S_DIM; i += 32) c += (int)flags[i];
            #pragma unroll
            for (int o = 16; o > 0; o >>= 1) c += __shfl_down_sync(0xffffffffu, c, o);
            if (t == 0) inv_count = 1.0f / (float)c;   // count >= 1 guaranteed
        }
        __syncthreads();

        if (active) {
            const float ic = inv_count;
            out[(size_t)b * VDIM + t] =
                make_float4(acc.x * ic, acc.y * ic, acc.z * ic, acc.w * ic);
        }
        __syncthreads();   // flags/inv_count reuse across reps
    }
}

extern "C" void kernel_launch(void* const* d_in, const int* in_sizes, int n_in,
                              void* d_out, int out_size) {
    (void)in_sizes; (void)n_in; (void)out_size;
    const float4* in = (const float4*)d_in[0];
    float4* out = (float4*)d_out;
    sentence_rep_kernel<<<GRID, NTHREADS>>>(in, out);
}